// round 12
// baseline (speedup 1.0000x reference)
#include <cuda_runtime.h>
#include <cuda_fp16.h>
#include <cstdint>

#define NB      256          // N_RES * EXPR flattened rows
#define NC      1025         // coeffs per row
#define NF      128          // frames
#define HOP     1024
#define NSAMP   131072
#define FPB     16           // frames per ifft block
#define NCHUNK  (NF / FPB)   // 8

// Scratch (allowed: __device__ globals, no runtime alloc)
__device__ __half2 g_spec[33587200];     // NB*NF*NC fp16 spectrum, 134MB

// ---------------------------------------------------------------------------
// Threefry-2x32 (20 rounds), JAX partitionable counter mode: key=(0,42),
// x=(0, i), output = v0 ^ v1.  Pure-SHF rotates — spec is TOTAL-ISSUE bound,
// so minimum instruction count wins (round-11 IMAD rebalance regressed).
// ---------------------------------------------------------------------------
__device__ __forceinline__ uint32_t threefry_xor(uint32_t x0, uint32_t x1) {
    const uint32_t ks0 = 0u, ks1 = 42u;
    const uint32_t ks2 = ks0 ^ ks1 ^ 0x1BD11BDAu;
    x0 += ks0; x1 += ks1;
#define TF_R(r) { x0 += x1; x1 = __funnelshift_l(x1, x1, (r)); x1 ^= x0; }
    TF_R(13) TF_R(15) TF_R(26) TF_R(6)
    x0 += ks1; x1 += ks2 + 1u;
    TF_R(17) TF_R(29) TF_R(16) TF_R(24)
    x0 += ks2; x1 += ks0 + 2u;
    TF_R(13) TF_R(15) TF_R(26) TF_R(6)
    x0 += ks0; x1 += ks1 + 3u;
    TF_R(17) TF_R(29) TF_R(16) TF_R(24)
    x0 += ks1; x1 += ks2 + 4u;
    TF_R(13) TF_R(15) TF_R(26) TF_R(6)
    x0 += ks2; x1 += ks0 + 5u;
#undef TF_R
    return x0 ^ x1;
}

// ---------------------------------------------------------------------------
// Kernel 1: spectrum synthesis
// ---------------------------------------------------------------------------
__global__ void __launch_bounds__(256) spec_kernel(
    const float* __restrict__ amp,   const float* __restrict__ phase,
    const float* __restrict__ decay, const float* __restrict__ dith)
{
    int gid = blockIdx.x * 256 + threadIdx.x;
    if (gid >= NB * NC) return;
    int b = gid / NC;
    int k = gid - b * NC;
    int pidx = (((b >> 2) * NC + k) << 2) + (b & 3);   // (N_RES, NC, EXPR) layout

    float a  = amp[pidx];
    float ph = phase[pidx];
    float dc = decay[pidx];
    float dt = dith[pidx];

    float sig = 1.0f / (1.0f + expf(-dc));
    float c   = 0.5f + (sig * 0.5f) * 0.99f;
    float m   = a * a;
    float sp  = tanhf(ph) * 3.14159274101257324f;
    float d   = tanhf(dt);

    uint32_t idx = (uint32_t)(b * NF) * (uint32_t)NC + (uint32_t)k;
    float acc = 0.0f;
    __half2* __restrict__ outp = g_spec + idx;

    #pragma unroll 4
    for (int t = 0; t < NF; t++) {
        uint32_t bits = threefry_xor(0u, idx);
        float f  = __uint_as_float((bits >> 9) | 0x3f800000u);  // [1,2)
        float nz = fmaf(f, 2.0f, -3.0f);   // == 2*(f-1)-1, exact, in [-1,1)
        acc += fmaf(d, nz, sp);
        m   *= c;

        float kq  = rintf(acc * 0.15915494309189535f);
        float red = fmaf(kq, -6.2831854820251465f, acc);
        red       = fmaf(kq,  1.7484555e-07f, red);
        float sn, cs;
        __sincosf(red, &sn, &cs);

        *outp = __floats2half2_rn(m * cs, m * sn);
        outp += NC;
        idx  += NC;
    }
}

// ---------------------------------------------------------------------------
// complex helpers
// ---------------------------------------------------------------------------
__device__ __forceinline__ float2 cadd(float2 a, float2 b){ return make_float2(a.x+b.x, a.y+b.y); }
__device__ __forceinline__ float2 csub(float2 a, float2 b){ return make_float2(a.x-b.x, a.y-b.y); }
__device__ __forceinline__ float2 cmul(float2 a, float2 b){
    return make_float2(a.x*b.x - a.y*b.y, a.x*b.y + a.y*b.x);
}
__device__ __forceinline__ float2 cmulc(float2 a, float cx, float cy){
    return make_float2(a.x*cx - a.y*cy, a.x*cy + a.y*cx);
}

__device__ __forceinline__ void radix4_inv(float2 a, float2 b, float2 c, float2 d,
                                           float2& t0, float2& t1, float2& t2, float2& t3)
{
    float2 apc = cadd(a, c), amc = csub(a, c);
    float2 bpd = cadd(b, d), bmd = csub(b, d);
    t0 = cadd(apc, bpd);
    t2 = csub(apc, bpd);
    t1 = make_float2(amc.x - bmd.y, amc.y + bmd.x);  // (a-c) + i(b-d)
    t3 = make_float2(amc.x + bmd.y, amc.y - bmd.x);  // (a-c) - i(b-d)
}

// Inverse 8-pt DFT (sign +i), natural order, IN PLACE on v[8].
__device__ __forceinline__ void dft8_inv_ip(float2 v[8])
{
    const float C = 0.70710678118654752f;
    float2 E0, E1, E2, E3, O0, O1, O2, O3;
    radix4_inv(v[0], v[2], v[4], v[6], E0, E1, E2, E3);
    radix4_inv(v[1], v[3], v[5], v[7], O0, O1, O2, O3);
    v[0] = cadd(E0, O0);            v[4] = csub(E0, O0);
    float2 t1 = cmulc(O1,  C, C);   // W8^1
    v[1] = cadd(E1, t1);            v[5] = csub(E1, t1);
    float2 t2 = make_float2(-O2.y, O2.x);   // i * O2
    v[2] = cadd(E2, t2);            v[6] = csub(E2, t2);
    float2 t3 = cmulc(O3, -C, C);   // W8^3
    v[3] = cadd(E3, t3);            v[7] = csub(E3, t3);
}

// e^{i pi j/8}, j=0..7 — fold per-j factor and stage-C twiddle W16^j.
__device__ __constant__ float E8C[8] = { 1.0f,  0.92387953251f,  0.70710678119f,  0.38268343236f,
                                         0.0f, -0.38268343236f, -0.70710678119f, -0.92387953251f };
__device__ __constant__ float E8S[8] = { 0.0f,  0.38268343236f,  0.70710678119f,  0.92387953251f,
                                         1.0f,  0.92387953251f,  0.70710678119f,  0.38268343236f };

// Stagger: conflict-free for all access patterns; STAG8(A+512)==STAG8(A)+512.
#define STAG8(A) ((A) ^ (((A) >> 3) & 15))

// ---------------------------------------------------------------------------
// Kernel 2: fused irfft + overlap-add (radix 8*8*8*2), 128 thr/frame.
// OLA carry lives in shared memory (prevS) — frees 8 registers/thread so the
// kernel fits 6 blocks/SM (reg cap 85).
// ---------------------------------------------------------------------------
__global__ void __launch_bounds__(128, 6) ifft_ola_kernel(float2* __restrict__ out2)
{
    __shared__ float2 bufA[1024];
    __shared__ float2 bufB[1024];
    __shared__ float2 prevS[512];              // [e*128 + u], conflict-free

    const int u       = threadIdx.x;          // 0..127
    const int b       = blockIdx.y;
    const int chunk   = blockIdx.x;
    const int t_start = chunk * FPB;
    const int t_first = (chunk == 0) ? 0 : t_start - 1;

    // hoisted frame-invariant twiddle bases
    float sb, cb;
    __sincosf((float)u * (3.14159265358979f / 1024.0f), &sb, &cb);
    const float2 fbase = make_float2(cb, sb);          // e^{i pi u/1024}
    const float2 w1A   = cmul(fbase, fbase);           // e^{2 pi i u/1024}
    const int    pB    = u >> 3;                       // 0..15
    float s2, c2;
    __sincosf((float)pB * (6.283185307179586f / 128.0f), &s2, &c2);
    const float2 w1B   = make_float2(c2, s2);          // e^{2 pi i pB/128}
    const int    pC    = (u >> 6) & 1;                 // warp-uniform

    #pragma unroll
    for (int e = 0; e < 4; e++) prevS[e * 128 + u] = make_float2(0.0f, 0.0f);
    // no sync needed: each thread only ever touches its own prevS slots

    for (int tf = t_first; tf < t_start + FPB; tf++) {
        const __half2* __restrict__ X = g_spec + (size_t)(b * NF + tf) * NC;

        // ---- prologue: Hermitian fold (1/2048 normalization folded in) ----
        float2 v[8];
        const float inv = 1.0f / 2048.0f;
        #pragma unroll
        for (int j = 0; j < 8; j++) {
            int k = u + 128 * j;
            float2 Xk = __half22float2(X[k]);
            float2 Xm = __half22float2(X[1024 - k]);
            if (k == 0) { Xk.y = 0.0f; Xm.y = 0.0f; }
            float Ax = (Xk.x + Xm.x) * inv;
            float Ay = (Xk.y - Xm.y) * inv;
            float Dx = (Xk.x - Xm.x) * inv;
            float Dy = (Xk.y + Xm.y) * inv;
            float2 fw = cmulc(fbase, E8C[j], E8S[j]);   // e^{i pi (u+128j)/1024}
            float Bx = Dx * fw.x - Dy * fw.y;
            float By = Dx * fw.y + Dy * fw.x;
            v[j] = make_float2(Ax - By, Ay + Bx);
        }

        // ---- stage A: radix-8, s=1, twiddle W1024^{u k} ----
        dft8_inv_ip(v);
        {
            const int ba = 8 * u;
            bufA[STAG8(ba)] = v[0];
            float2 w = w1A;
            #pragma unroll
            for (int k = 1; k < 8; k++) {
                bufA[STAG8(ba + k)] = cmul(v[k], w);
                if (k < 7) w = cmul(w, w1A);
            }
        }
        __syncthreads();

        // ---- stage B: radix-8, s=8, twiddle W128^{pB k} ----
        #pragma unroll
        for (int j = 0; j < 8; j++) v[j] = bufA[STAG8(u + 128 * j)];
        dft8_inv_ip(v);
        {
            const int bb = (u & 7) + 64 * pB;           // q + 64 p
            bufB[STAG8(bb)] = v[0];
            float2 w = w1B;
            #pragma unroll
            for (int k = 1; k < 8; k++) {
                bufB[STAG8(bb + 8 * k)] = cmul(v[k], w);
                if (k < 7) w = cmul(w, w1B);
            }
        }
        __syncthreads();

        // ---- stage C: radix-8, s=64, twiddle W16^{pC k} (constants) ----
        #pragma unroll
        for (int j = 0; j < 8; j++) v[j] = bufB[STAG8(u + 128 * j)];
        dft8_inv_ip(v);
        {
            const int bc = (u & 63) + 512 * pC;         // q + 512 p
            if (pC) {                                    // warp-uniform branch
                #pragma unroll
                for (int k = 1; k < 8; k++) v[k] = cmulc(v[k], E8C[k], E8S[k]);
            }
            #pragma unroll
            for (int k = 0; k < 8; k++)
                bufA[STAG8(bc + 64 * k)] = v[k];
        }
        __syncthreads();

        // ---- stage D: radix-2, s=512, twiddle-free, fused with OLA ----
        const int obase = b * (NSAMP / 2) + tf * 512;
        #pragma unroll
        for (int e = 0; e < 4; e++) {
            int u4 = u + 128 * e;
            int sp = STAG8(u4);
            float2 a  = bufA[sp];
            float2 bb = bufA[sp + 512];
            float2 t0 = cadd(a, bb);                    // pair u4 (first half)
            float2 t1 = csub(a, bb);                    // pair u4+512 (second half)
            if (tf >= t_start) {
                float2 pv = prevS[e * 128 + u];
                out2[obase + u4] = make_float2(t0.x + pv.x, t0.y + pv.y);
            }
            prevS[e * 128 + u] = t1;
        }
        __syncthreads();   // bufA reused by next frame's stage-A writes
    }
}

// ---------------------------------------------------------------------------
extern "C" void kernel_launch(void* const* d_in, const int* in_sizes, int n_in,
                              void* d_out, int out_size)
{
    const float* amp   = (const float*)d_in[0];
    const float* phase = (const float*)d_in[1];
    const float* decay = (const float*)d_in[2];
    const float* dith  = (const float*)d_in[3];
    float2* out2 = (float2*)d_out;

    spec_kernel<<<(NB * NC + 255) / 256, 256>>>(amp, phase, decay, dith);
    dim3 grid2(NCHUNK, NB);
    ifft_ola_kernel<<<grid2, 128>>>(out2);
}

// round 13
// speedup vs baseline: 1.5962x; 1.5962x over previous
#include <cuda_runtime.h>
#include <cuda_fp16.h>
#include <cstdint>

#define NB      256          // N_RES * EXPR flattened rows
#define NC      1025         // coeffs per row
#define NF      128          // frames
#define HOP     1024
#define NSAMP   131072
#define FPB     16           // frames per ifft block
#define NCHUNK  (NF / FPB)   // 8

// Scratch (allowed: __device__ globals, no runtime alloc)
__device__ __half2 g_spec[33587200];     // NB*NF*NC fp16 spectrum, 134MB

// ---------------------------------------------------------------------------
// Threefry-2x32 (20 rounds), JAX partitionable counter mode: key=(0,42),
// x=(0, i), output = v0 ^ v1.  Pure-SHF rotates (minimum instruction count;
// spec is total-issue-bound — R11's IMAD rebalance regressed).
// ---------------------------------------------------------------------------
__device__ __forceinline__ uint32_t threefry_xor(uint32_t x0, uint32_t x1) {
    const uint32_t ks0 = 0u, ks1 = 42u;
    const uint32_t ks2 = ks0 ^ ks1 ^ 0x1BD11BDAu;
    x0 += ks0; x1 += ks1;
#define TF_R(r) { x0 += x1; x1 = __funnelshift_l(x1, x1, (r)); x1 ^= x0; }
    TF_R(13) TF_R(15) TF_R(26) TF_R(6)
    x0 += ks1; x1 += ks2 + 1u;
    TF_R(17) TF_R(29) TF_R(16) TF_R(24)
    x0 += ks2; x1 += ks0 + 2u;
    TF_R(13) TF_R(15) TF_R(26) TF_R(6)
    x0 += ks0; x1 += ks1 + 3u;
    TF_R(17) TF_R(29) TF_R(16) TF_R(24)
    x0 += ks1; x1 += ks2 + 4u;
    TF_R(13) TF_R(15) TF_R(26) TF_R(6)
    x0 += ks2; x1 += ks0 + 5u;
#undef TF_R
    return x0 ^ x1;
}

// ---------------------------------------------------------------------------
// Kernel 1: spectrum synthesis (round-8 configuration)
// ---------------------------------------------------------------------------
__global__ void __launch_bounds__(256) spec_kernel(
    const float* __restrict__ amp,   const float* __restrict__ phase,
    const float* __restrict__ decay, const float* __restrict__ dith)
{
    int gid = blockIdx.x * 256 + threadIdx.x;
    if (gid >= NB * NC) return;
    int b = gid / NC;
    int k = gid - b * NC;
    int pidx = (((b >> 2) * NC + k) << 2) + (b & 3);   // (N_RES, NC, EXPR) layout

    float a  = amp[pidx];
    float ph = phase[pidx];
    float dc = decay[pidx];
    float dt = dith[pidx];

    float sig = 1.0f / (1.0f + expf(-dc));
    float c   = 0.5f + (sig * 0.5f) * 0.99f;
    float m   = a * a;
    float sp  = tanhf(ph) * 3.14159274101257324f;
    float d   = tanhf(dt);

    uint32_t idx = (uint32_t)(b * NF) * (uint32_t)NC + (uint32_t)k;
    float acc = 0.0f;
    __half2* __restrict__ outp = g_spec + idx;

    #pragma unroll 4
    for (int t = 0; t < NF; t++) {
        uint32_t bits = threefry_xor(0u, idx);
        float f  = __uint_as_float((bits >> 9) | 0x3f800000u);  // [1,2)
        float nz = fmaf(f, 2.0f, -3.0f);   // == 2*(f-1)-1, exact, in [-1,1)
        acc += fmaf(d, nz, sp);
        m   *= c;

        float kq  = rintf(acc * 0.15915494309189535f);
        float red = fmaf(kq, -6.2831854820251465f, acc);
        red       = fmaf(kq,  1.7484555e-07f, red);
        float sn, cs;
        __sincosf(red, &sn, &cs);

        *outp = __floats2half2_rn(m * cs, m * sn);
        outp += NC;
        idx  += NC;
    }
}

// ---------------------------------------------------------------------------
// complex helpers
// ---------------------------------------------------------------------------
__device__ __forceinline__ float2 cadd(float2 a, float2 b){ return make_float2(a.x+b.x, a.y+b.y); }
__device__ __forceinline__ float2 csub(float2 a, float2 b){ return make_float2(a.x-b.x, a.y-b.y); }
__device__ __forceinline__ float2 cmul(float2 a, float2 b){
    return make_float2(a.x*b.x - a.y*b.y, a.x*b.y + a.y*b.x);
}
__device__ __forceinline__ float2 cmulc(float2 a, float cx, float cy){
    return make_float2(a.x*cx - a.y*cy, a.x*cy + a.y*cx);
}

__device__ __forceinline__ void radix4_inv(float2 a, float2 b, float2 c, float2 d,
                                           float2& t0, float2& t1, float2& t2, float2& t3)
{
    float2 apc = cadd(a, c), amc = csub(a, c);
    float2 bpd = cadd(b, d), bmd = csub(b, d);
    t0 = cadd(apc, bpd);
    t2 = csub(apc, bpd);
    t1 = make_float2(amc.x - bmd.y, amc.y + bmd.x);  // (a-c) + i(b-d)
    t3 = make_float2(amc.x + bmd.y, amc.y - bmd.x);  // (a-c) - i(b-d)
}

// Inverse 8-pt DFT (sign +i), natural order, IN PLACE on v[8].
__device__ __forceinline__ void dft8_inv_ip(float2 v[8])
{
    const float C = 0.70710678118654752f;
    float2 E0, E1, E2, E3, O0, O1, O2, O3;
    radix4_inv(v[0], v[2], v[4], v[6], E0, E1, E2, E3);
    radix4_inv(v[1], v[3], v[5], v[7], O0, O1, O2, O3);
    v[0] = cadd(E0, O0);            v[4] = csub(E0, O0);
    float2 t1 = cmulc(O1,  C, C);   // W8^1
    v[1] = cadd(E1, t1);            v[5] = csub(E1, t1);
    float2 t2 = make_float2(-O2.y, O2.x);   // i * O2
    v[2] = cadd(E2, t2);            v[6] = csub(E2, t2);
    float2 t3 = cmulc(O3, -C, C);   // W8^3
    v[3] = cadd(E3, t3);            v[7] = csub(E3, t3);
}

// e^{i pi j/8}, j=0..7 — fold per-j factor and stage-C twiddle W16^j.
__device__ __constant__ float E8C[8] = { 1.0f,  0.92387953251f,  0.70710678119f,  0.38268343236f,
                                         0.0f, -0.38268343236f, -0.70710678119f, -0.92387953251f };
__device__ __constant__ float E8S[8] = { 0.0f,  0.38268343236f,  0.70710678119f,  0.92387953251f,
                                         1.0f,  0.92387953251f,  0.70710678119f,  0.38268343236f };

// Stagger: conflict-free for all access patterns; STAG8(A+512)==STAG8(A)+512.
#define STAG8(A) ((A) ^ (((A) >> 3) & 15))

// ---------------------------------------------------------------------------
// Kernel 2: fused irfft + overlap-add (radix 8*8*8*2), 128 thr/frame,
// in-place butterflies, register OLA carry, NO min-blocks pin (natural 88
// regs, 5 blocks/SM — round-11 measured configuration: 104.1 us).
// ---------------------------------------------------------------------------
__global__ void __launch_bounds__(128) ifft_ola_kernel(float2* __restrict__ out2)
{
    __shared__ float2 bufA[1024];
    __shared__ float2 bufB[1024];

    const int u       = threadIdx.x;          // 0..127
    const int b       = blockIdx.y;
    const int chunk   = blockIdx.x;
    const int t_start = chunk * FPB;
    const int t_first = (chunk == 0) ? 0 : t_start - 1;

    // hoisted frame-invariant twiddle bases
    float sb, cb;
    __sincosf((float)u * (3.14159265358979f / 1024.0f), &sb, &cb);
    const float2 fbase = make_float2(cb, sb);          // e^{i pi u/1024}
    const float2 w1A   = cmul(fbase, fbase);           // e^{2 pi i u/1024}
    const int    pB    = u >> 3;                       // 0..15
    float s2, c2;
    __sincosf((float)pB * (6.283185307179586f / 128.0f), &s2, &c2);
    const float2 w1B   = make_float2(c2, s2);          // e^{2 pi i pB/128}
    const int    pC    = (u >> 6) & 1;                 // warp-uniform

    float2 prev[4];
    #pragma unroll
    for (int e = 0; e < 4; e++) prev[e] = make_float2(0.0f, 0.0f);

    for (int tf = t_first; tf < t_start + FPB; tf++) {
        const __half2* __restrict__ X = g_spec + (size_t)(b * NF + tf) * NC;

        // ---- prologue: Hermitian fold (1/2048 normalization folded in) ----
        float2 v[8];
        const float inv = 1.0f / 2048.0f;
        #pragma unroll
        for (int j = 0; j < 8; j++) {
            int k = u + 128 * j;
            float2 Xk = __half22float2(X[k]);
            float2 Xm = __half22float2(X[1024 - k]);
            if (k == 0) { Xk.y = 0.0f; Xm.y = 0.0f; }
            float Ax = (Xk.x + Xm.x) * inv;
            float Ay = (Xk.y - Xm.y) * inv;
            float Dx = (Xk.x - Xm.x) * inv;
            float Dy = (Xk.y + Xm.y) * inv;
            float2 fw = cmulc(fbase, E8C[j], E8S[j]);   // e^{i pi (u+128j)/1024}
            float Bx = Dx * fw.x - Dy * fw.y;
            float By = Dx * fw.y + Dy * fw.x;
            v[j] = make_float2(Ax - By, Ay + Bx);
        }

        // ---- stage A: radix-8, s=1, twiddle W1024^{u k} ----
        dft8_inv_ip(v);
        {
            const int ba = 8 * u;
            bufA[STAG8(ba)] = v[0];
            float2 w = w1A;
            #pragma unroll
            for (int k = 1; k < 8; k++) {
                bufA[STAG8(ba + k)] = cmul(v[k], w);
                if (k < 7) w = cmul(w, w1A);
            }
        }
        __syncthreads();

        // ---- stage B: radix-8, s=8, twiddle W128^{pB k} ----
        #pragma unroll
        for (int j = 0; j < 8; j++) v[j] = bufA[STAG8(u + 128 * j)];
        dft8_inv_ip(v);
        {
            const int bb = (u & 7) + 64 * pB;           // q + 64 p
            bufB[STAG8(bb)] = v[0];
            float2 w = w1B;
            #pragma unroll
            for (int k = 1; k < 8; k++) {
                bufB[STAG8(bb + 8 * k)] = cmul(v[k], w);
                if (k < 7) w = cmul(w, w1B);
            }
        }
        __syncthreads();

        // ---- stage C: radix-8, s=64, twiddle W16^{pC k} (constants) ----
        #pragma unroll
        for (int j = 0; j < 8; j++) v[j] = bufB[STAG8(u + 128 * j)];
        dft8_inv_ip(v);
        {
            const int bc = (u & 63) + 512 * pC;         // q + 512 p
            if (pC) {                                    // warp-uniform branch
                #pragma unroll
                for (int k = 1; k < 8; k++) v[k] = cmulc(v[k], E8C[k], E8S[k]);
            }
            #pragma unroll
            for (int k = 0; k < 8; k++)
                bufA[STAG8(bc + 64 * k)] = v[k];
        }
        __syncthreads();

        // ---- stage D: radix-2, s=512, twiddle-free, fused with OLA ----
        const int obase = b * (NSAMP / 2) + tf * 512;
        #pragma unroll
        for (int e = 0; e < 4; e++) {
            int u4 = u + 128 * e;
            int sp = STAG8(u4);
            float2 a  = bufA[sp];
            float2 bb = bufA[sp + 512];
            float2 t0 = cadd(a, bb);                    // pair u4 (first half)
            float2 t1 = csub(a, bb);                    // pair u4+512 (second half)
            if (tf >= t_start)
                out2[obase + u4] = make_float2(t0.x + prev[e].x, t0.y + prev[e].y);
            prev[e] = t1;
        }
        __syncthreads();   // bufA reused by next frame's stage-A writes
    }
}

// ---------------------------------------------------------------------------
extern "C" void kernel_launch(void* const* d_in, const int* in_sizes, int n_in,
                              void* d_out, int out_size)
{
    const float* amp   = (const float*)d_in[0];
    const float* phase = (const float*)d_in[1];
    const float* decay = (const float*)d_in[2];
    const float* dith  = (const float*)d_in[3];
    float2* out2 = (float2*)d_out;

    spec_kernel<<<(NB * NC + 255) / 256, 256>>>(amp, phase, decay, dith);
    dim3 grid2(NCHUNK, NB);
    ifft_ola_kernel<<<grid2, 128>>>(out2);
}

// round 15
// speedup vs baseline: 1.7607x; 1.1030x over previous
#include <cuda_runtime.h>
#include <cuda_fp16.h>
#include <cstdint>

#define NB      256          // N_RES * EXPR flattened rows
#define NC      1025         // coeffs per row
#define NF      128          // frames
#define HOP     1024
#define NSAMP   131072
#define FPB     16           // frames per ifft block
#define NCHUNK  (NF / FPB)   // 8

// Scratch (allowed: __device__ globals, no runtime alloc)
__device__ __half2 g_spec[33587200];     // NB*NF*NC fp16 spectrum, 134MB

// ---------------------------------------------------------------------------
// Threefry-2x32 (20 rounds), JAX partitionable counter mode: key=(0,42),
// x=(0, i), output = v0 ^ v1.  Pure-SHF rotates (minimum instruction count).
// ---------------------------------------------------------------------------
__device__ __forceinline__ uint32_t threefry_xor(uint32_t x0, uint32_t x1) {
    const uint32_t ks0 = 0u, ks1 = 42u;
    const uint32_t ks2 = ks0 ^ ks1 ^ 0x1BD11BDAu;
    x0 += ks0; x1 += ks1;
#define TF_R(r) { x0 += x1; x1 = __funnelshift_l(x1, x1, (r)); x1 ^= x0; }
    TF_R(13) TF_R(15) TF_R(26) TF_R(6)
    x0 += ks1; x1 += ks2 + 1u;
    TF_R(17) TF_R(29) TF_R(16) TF_R(24)
    x0 += ks2; x1 += ks0 + 2u;
    TF_R(13) TF_R(15) TF_R(26) TF_R(6)
    x0 += ks0; x1 += ks1 + 3u;
    TF_R(17) TF_R(29) TF_R(16) TF_R(24)
    x0 += ks1; x1 += ks2 + 4u;
    TF_R(13) TF_R(15) TF_R(26) TF_R(6)
    x0 += ks2; x1 += ks0 + 5u;
#undef TF_R
    return x0 ^ x1;
}

// ---------------------------------------------------------------------------
// Kernel 1: spectrum synthesis with fp16-underflow early exit.
// m_t = a^2 * c^t decays monotonically (c < 1). Once every lane of the warp
// has m < 2.9e-8 < 2^-25, all remaining __floats2half2_rn outputs are exactly
// zero regardless of phase -> break and zero-fill (bit-identical spectrum).
// Grid is exactly NB*NC = 1025 blocks * 256 threads: no partial warps, full
// ballot mask is safe.
// ---------------------------------------------------------------------------
__global__ void __launch_bounds__(256) spec_kernel(
    const float* __restrict__ amp,   const float* __restrict__ phase,
    const float* __restrict__ decay, const float* __restrict__ dith)
{
    int gid = blockIdx.x * 256 + threadIdx.x;
    int b = gid / NC;
    int k = gid - b * NC;
    int pidx = (((b >> 2) * NC + k) << 2) + (b & 3);   // (N_RES, NC, EXPR) layout

    float a  = amp[pidx];
    float ph = phase[pidx];
    float dc = decay[pidx];
    float dt = dith[pidx];

    float sig = 1.0f / (1.0f + expf(-dc));
    float c   = 0.5f + (sig * 0.5f) * 0.99f;
    float m   = a * a;
    float sp  = tanhf(ph) * 3.14159274101257324f;
    float d   = tanhf(dt);

    uint32_t idx = (uint32_t)(b * NF) * (uint32_t)NC + (uint32_t)k;
    float acc = 0.0f;
    __half2* __restrict__ outp = g_spec + idx;

    int t = 0;
    #pragma unroll 4
    for (; t < NF; t++) {
        uint32_t bits = threefry_xor(0u, idx);
        float f  = __uint_as_float((bits >> 9) | 0x3f800000u);  // [1,2)
        float nz = fmaf(f, 2.0f, -3.0f);   // == 2u-1, exact, in [-1,1)
        acc += fmaf(d, nz, sp);
        m   *= c;

        float kq  = rintf(acc * 0.15915494309189535f);
        float red = fmaf(kq, -6.2831854820251465f, acc);
        red       = fmaf(kq,  1.7484555e-07f, red);
        float sn, cs;
        __sincosf(red, &sn, &cs);

        *outp = __floats2half2_rn(m * cs, m * sn);
        outp += NC;
        idx  += NC;

        // every 4th frame: if the whole warp has underflowed fp16, stop
        if ((t & 3) == 3) {
            if (__ballot_sync(0xffffffffu, m >= 2.9e-8f) == 0u) { t++; break; }
        }
    }
    // remaining frames: outputs are exactly fp16 zero — store-only loop
    const __half2 z = __float2half2_rn(0.0f);
    for (; t < NF; t++) {
        *outp = z;
        outp += NC;
    }
}

// ---------------------------------------------------------------------------
// complex helpers
// ---------------------------------------------------------------------------
__device__ __forceinline__ float2 cadd(float2 a, float2 b){ return make_float2(a.x+b.x, a.y+b.y); }
__device__ __forceinline__ float2 csub(float2 a, float2 b){ return make_float2(a.x-b.x, a.y-b.y); }
__device__ __forceinline__ float2 cmul(float2 a, float2 b){
    return make_float2(a.x*b.x - a.y*b.y, a.x*b.y + a.y*b.x);
}
__device__ __forceinline__ float2 cmulc(float2 a, float cx, float cy){
    return make_float2(a.x*cx - a.y*cy, a.x*cy + a.y*cx);
}

__device__ __forceinline__ void radix4_inv(float2 a, float2 b, float2 c, float2 d,
                                           float2& t0, float2& t1, float2& t2, float2& t3)
{
    float2 apc = cadd(a, c), amc = csub(a, c);
    float2 bpd = cadd(b, d), bmd = csub(b, d);
    t0 = cadd(apc, bpd);
    t2 = csub(apc, bpd);
    t1 = make_float2(amc.x - bmd.y, amc.y + bmd.x);  // (a-c) + i(b-d)
    t3 = make_float2(amc.x + bmd.y, amc.y - bmd.x);  // (a-c) - i(b-d)
}

// Inverse 8-pt DFT (sign +i), natural order, IN PLACE on v[8].
__device__ __forceinline__ void dft8_inv_ip(float2 v[8])
{
    const float C = 0.70710678118654752f;
    float2 E0, E1, E2, E3, O0, O1, O2, O3;
    radix4_inv(v[0], v[2], v[4], v[6], E0, E1, E2, E3);
    radix4_inv(v[1], v[3], v[5], v[7], O0, O1, O2, O3);
    v[0] = cadd(E0, O0);            v[4] = csub(E0, O0);
    float2 t1 = cmulc(O1,  C, C);   // W8^1
    v[1] = cadd(E1, t1);            v[5] = csub(E1, t1);
    float2 t2 = make_float2(-O2.y, O2.x);   // i * O2
    v[2] = cadd(E2, t2);            v[6] = csub(E2, t2);
    float2 t3 = cmulc(O3, -C, C);   // W8^3
    v[3] = cadd(E3, t3);            v[7] = csub(E3, t3);
}

// e^{i pi j/8}, j=0..7 — fold per-j factor and stage-C twiddle W16^j.
__device__ __constant__ float E8C[8] = { 1.0f,  0.92387953251f,  0.70710678119f,  0.38268343236f,
                                         0.0f, -0.38268343236f, -0.70710678119f, -0.92387953251f };
__device__ __constant__ float E8S[8] = { 0.0f,  0.38268343236f,  0.70710678119f,  0.92387953251f,
                                         1.0f,  0.92387953251f,  0.70710678119f,  0.38268343236f };

// Stagger: conflict-free for all access patterns; STAG8(A+512)==STAG8(A)+512.
#define STAG8(A) ((A) ^ (((A) >> 3) & 15))

// ---------------------------------------------------------------------------
// Kernel 2: fused irfft + overlap-add (radix 8*8*8*2), 128 thr/frame.
// Round-11 measured configuration: in-place butterflies, register OLA carry,
// __launch_bounds__(128, 5) -> 88 regs, 5 blocks/SM, 104.1 us.
// ---------------------------------------------------------------------------
__global__ void __launch_bounds__(128, 5) ifft_ola_kernel(float2* __restrict__ out2)
{
    __shared__ float2 bufA[1024];
    __shared__ float2 bufB[1024];

    const int u       = threadIdx.x;          // 0..127
    const int b       = blockIdx.y;
    const int chunk   = blockIdx.x;
    const int t_start = chunk * FPB;
    const int t_first = (chunk == 0) ? 0 : t_start - 1;

    // hoisted frame-invariant twiddle bases
    float sb, cb;
    __sincosf((float)u * (3.14159265358979f / 1024.0f), &sb, &cb);
    const float2 fbase = make_float2(cb, sb);          // e^{i pi u/1024}
    const float2 w1A   = cmul(fbase, fbase);           // e^{2 pi i u/1024}
    const int    pB    = u >> 3;                       // 0..15
    float s2, c2;
    __sincosf((float)pB * (6.283185307179586f / 128.0f), &s2, &c2);
    const float2 w1B   = make_float2(c2, s2);          // e^{2 pi i pB/128}
    const int    pC    = (u >> 6) & 1;                 // warp-uniform

    float2 prev[4];
    #pragma unroll
    for (int e = 0; e < 4; e++) prev[e] = make_float2(0.0f, 0.0f);

    for (int tf = t_first; tf < t_start + FPB; tf++) {
        const __half2* __restrict__ X = g_spec + (size_t)(b * NF + tf) * NC;

        // ---- prologue: Hermitian fold (1/2048 normalization folded in) ----
        float2 v[8];
        const float inv = 1.0f / 2048.0f;
        #pragma unroll
        for (int j = 0; j < 8; j++) {
            int k = u + 128 * j;
            float2 Xk = __half22float2(X[k]);
            float2 Xm = __half22float2(X[1024 - k]);
            if (k == 0) { Xk.y = 0.0f; Xm.y = 0.0f; }
            float Ax = (Xk.x + Xm.x) * inv;
            float Ay = (Xk.y - Xm.y) * inv;
            float Dx = (Xk.x - Xm.x) * inv;
            float Dy = (Xk.y + Xm.y) * inv;
            float2 fw = cmulc(fbase, E8C[j], E8S[j]);   // e^{i pi (u+128j)/1024}
            float Bx = Dx * fw.x - Dy * fw.y;
            float By = Dx * fw.y + Dy * fw.x;
            v[j] = make_float2(Ax - By, Ay + Bx);
        }

        // ---- stage A: radix-8, s=1, twiddle W1024^{u k} ----
        dft8_inv_ip(v);
        {
            const int ba = 8 * u;
            bufA[STAG8(ba)] = v[0];
            float2 w = w1A;
            #pragma unroll
            for (int k = 1; k < 8; k++) {
                bufA[STAG8(ba + k)] = cmul(v[k], w);
                if (k < 7) w = cmul(w, w1A);
            }
        }
        __syncthreads();

        // ---- stage B: radix-8, s=8, twiddle W128^{pB k} ----
        #pragma unroll
        for (int j = 0; j < 8; j++) v[j] = bufA[STAG8(u + 128 * j)];
        dft8_inv_ip(v);
        {
            const int bb = (u & 7) + 64 * pB;           // q + 64 p
            bufB[STAG8(bb)] = v[0];
            float2 w = w1B;
            #pragma unroll
            for (int k = 1; k < 8; k++) {
                bufB[STAG8(bb + 8 * k)] = cmul(v[k], w);
                if (k < 7) w = cmul(w, w1B);
            }
        }
        __syncthreads();

        // ---- stage C: radix-8, s=64, twiddle W16^{pC k} (constants) ----
        #pragma unroll
        for (int j = 0; j < 8; j++) v[j] = bufB[STAG8(u + 128 * j)];
        dft8_inv_ip(v);
        {
            const int bc = (u & 63) + 512 * pC;         // q + 512 p
            if (pC) {                                    // warp-uniform branch
                #pragma unroll
                for (int k = 1; k < 8; k++) v[k] = cmulc(v[k], E8C[k], E8S[k]);
            }
            #pragma unroll
            for (int k = 0; k < 8; k++)
                bufA[STAG8(bc + 64 * k)] = v[k];
        }
        __syncthreads();

        // ---- stage D: radix-2, s=512, twiddle-free, fused with OLA ----
        const int obase = b * (NSAMP / 2) + tf * 512;
        #pragma unroll
        for (int e = 0; e < 4; e++) {
            int u4 = u + 128 * e;
            int sp = STAG8(u4);
            float2 a  = bufA[sp];
            float2 bb = bufA[sp + 512];
            float2 t0 = cadd(a, bb);                    // pair u4 (first half)
            float2 t1 = csub(a, bb);                    // pair u4+512 (second half)
            if (tf >= t_start)
                out2[obase + u4] = make_float2(t0.x + prev[e].x, t0.y + prev[e].y);
            prev[e] = t1;
        }
        __syncthreads();   // bufA reused by next frame's stage-A writes
    }
}

// ---------------------------------------------------------------------------
extern "C" void kernel_launch(void* const* d_in, const int* in_sizes, int n_in,
                              void* d_out, int out_size)
{
    const float* amp   = (const float*)d_in[0];
    const float* phase = (const float*)d_in[1];
    const float* decay = (const float*)d_in[2];
    const float* dith  = (const float*)d_in[3];
    float2* out2 = (float2*)d_out;

    spec_kernel<<<(NB * NC + 255) / 256, 256>>>(amp, phase, decay, dith);
    dim3 grid2(NCHUNK, NB);
    ifft_ola_kernel<<<grid2, 128>>>(out2);
}